// round 9
// baseline (speedup 1.0000x reference)
#include <cuda_runtime.h>
#include <cuda_bf16.h>
#include <math.h>
#include <stdint.h>

// Shapes (fixed by the problem)
#define BB      2
#define TT_SEQ  1024
#define DM      768
#define DI      1536        // D_INNER
#define DS      16          // D_STATE
#define DR      48          // DT_RANK
#define TOK     (BB*TT_SEQ) // 2048
#define XPROJ_N (DR + 2*DS) // 80
#define KSPLIT  8
#define PART_STRIDE (TOK * XPROJ_N)   // 163840

// -------- device scratch (no allocs allowed) --------
__device__ __nv_bfloat16  g_xz       [TOK * 2 * DI];
__device__ float          g_xdbl     [TOK * XPROJ_N];
__device__ float          g_xdbl_part[KSPLIT * PART_STRIDE];
__device__ __nv_bfloat16  g_dt_bf    [TOK * DI];
__device__ __nv_bfloat16  g_h_bf     [TOK * DM];
__device__ __nv_bfloat16  g_xc_bf    [TOK * DI];
__device__ __nv_bfloat16  g_dtr_bf   [TOK * DR];
__device__ __nv_bfloat16  g_y_bf     [TOK * DI];
__device__ __nv_bfloat16  g_Win_bf   [2 * DI * DM];
__device__ __nv_bfloat16  g_Wxp_bf   [XPROJ_N * DI];
__device__ __nv_bfloat16  g_Wdt_bf   [DI * DR];
__device__ __nv_bfloat16  g_Wout_bf  [DM * DI];

// ===========================================================================
// Helpers
// ===========================================================================
__device__ __forceinline__ void cp16(uint32_t dst, const void* src, int bytes) {
    asm volatile("cp.async.cg.shared.global [%0], [%1], 16, %2;"
                 :: "r"(dst), "l"(src), "r"(bytes) : "memory");
}
#define CP_COMMIT() asm volatile("cp.async.commit_group;" ::: "memory")
#define CP_WAIT(n)  asm volatile("cp.async.wait_group %0;" :: "n"(n) : "memory")

__device__ __forceinline__ uint32_t smem_u32(const void* p) {
    uint32_t a;
    asm("{ .reg .u64 t; cvta.to.shared.u64 t, %1; cvt.u32.u64 %0, t; }"
        : "=r"(a) : "l"(p));
    return a;
}

__device__ __forceinline__ void mma_bf16(float* c, const uint32_t* a, const uint32_t* b) {
    asm volatile(
        "mma.sync.aligned.m16n8k16.row.col.f32.bf16.bf16.f32 "
        "{%0,%1,%2,%3}, {%4,%5,%6,%7}, {%8,%9}, {%0,%1,%2,%3};"
        : "+f"(c[0]), "+f"(c[1]), "+f"(c[2]), "+f"(c[3])
        : "r"(a[0]), "r"(a[1]), "r"(a[2]), "r"(a[3]), "r"(b[0]), "r"(b[1]));
}

__device__ __forceinline__ void ldsm_x4(uint32_t* r, uint32_t addr) {
    asm volatile("ldmatrix.sync.aligned.m8n8.x4.shared.b16 {%0,%1,%2,%3}, [%4];"
        : "=r"(r[0]), "=r"(r[1]), "=r"(r[2]), "=r"(r[3]) : "r"(addr));
}

__device__ __forceinline__ float softplus_f(float v) {
    return (v > 20.f) ? v : __logf(1.f + __expf(v));
}
__device__ __forceinline__ float silu_f(float v) {
    return __fdividef(v, 1.f + __expf(-v));
}

// ===========================================================================
// bf16 mma.sync GEMM with ldmatrix fragment loads, 3-stage cp.async pipeline.
// C = A(M x K, lda) * B(N x K, ldb)^T. Block tile 128x128, BK=32,
// 128 threads = 4 warps (2Mx2N), warp tile 64x64. Smem rows 80B.
// MODE 0: store bf16. MODE 1: softplus(+ep[col]) -> bf16.
// MODE 2: +ep[row*ldc+col] fp32. MODE 3: store fp32 (split-K partials).
// ===========================================================================
#define PITCHB 80
#define TILE_B (128 * PITCHB)
#define BUF_B  (2 * TILE_B)
#define NSTAGE 3
#define GEMM_SMEM_BYTES (NSTAGE * BUF_B)     // 61440

template<int MODE>
__global__ void __launch_bounds__(128, 2) gemm_mma_kernel(
    const __nv_bfloat16* __restrict__ A, int lda,
    const __nv_bfloat16* __restrict__ B, int ldb,
    void* __restrict__ Cv, int ldc,
    const float* __restrict__ ep,
    int N, int Ktotal, int ksplit, size_t zstride)
{
    extern __shared__ char smem[];
    const int tid = threadIdx.x;
    const int wid = tid >> 5, lid = tid & 31;
    const int g = lid >> 2, tig = lid & 3;
    const int warp_m = (wid & 1) * 64;
    const int warp_n = (wid >> 1) * 64;
    const int m0 = blockIdx.y * 128;
    const int n0 = blockIdx.x * 128;
    const int kbeg = blockIdx.z * ksplit;
    const int kend = min(kbeg + ksplit, Ktotal);

    const uint32_t sbase = smem_u32(smem);
    const uint32_t aoff = (uint32_t)((warp_m + (lid & 15)) * PITCHB + ((lid >> 4) << 4));
    const uint32_t boff = (uint32_t)((warp_n + (lid & 7) + ((lid >> 4) & 1) * 8) * PITCHB
                                     + ((lid >> 3) & 1) * 16);

    float acc[4][8][4];
#pragma unroll
    for (int i = 0; i < 4; i++)
#pragma unroll
        for (int j = 0; j < 8; j++)
#pragma unroll
            for (int q = 0; q < 4; q++) acc[i][j][q] = 0.f;

    const int NT = (kend - kbeg + 31) >> 5;

    auto load_tiles = [&](int it) {
        const int buf = it % NSTAGE;
        const int k0 = kbeg + it * 32;
        const uint32_t sA = sbase + (uint32_t)buf * BUF_B;
        const uint32_t sB = sA + TILE_B;
#pragma unroll
        for (int j = 0; j < 4; j++) {
            int idx = tid + j * 128;           // 0..511
            int r = idx >> 2, c8 = (idx & 3) * 8;
            int kk = k0 + c8;
            int bytes = min(max(kend - kk, 0), 8) * 2;
            int ksafe = bytes ? kk : k0;
            cp16(sA + (uint32_t)(r * PITCHB + c8 * 2),
                 A + (size_t)(m0 + r) * lda + ksafe, bytes);
            int nr = n0 + r;
            int bytesB = (nr < N) ? bytes : 0;
            cp16(sB + (uint32_t)(r * PITCHB + c8 * 2),
                 B + (size_t)((nr < N) ? nr : 0) * ldb + ksafe, bytesB);
        }
        CP_COMMIT();
    };

    load_tiles(0);
    if (NT > 1) load_tiles(1);

    for (int it = 0; it < NT; it++) {
        if (it + 2 < NT) { load_tiles(it + 2); CP_WAIT(2); }
        else if (it + 1 < NT) { CP_WAIT(1); }
        else { CP_WAIT(0); }
        __syncthreads();

        const uint32_t sA = sbase + (uint32_t)(it % NSTAGE) * BUF_B;
        const uint32_t a_base = sA + aoff;
        const uint32_t b_base = sA + TILE_B + boff;
#pragma unroll
        for (int ks = 0; ks < 2; ks++) {
            uint32_t a[4][4], bb[4][4];
#pragma unroll
            for (int ma = 0; ma < 4; ma++)
                ldsm_x4(a[ma], a_base + (uint32_t)(ma * 16 * PITCHB + ks * 32));
#pragma unroll
            for (int np = 0; np < 4; np++)
                ldsm_x4(bb[np], b_base + (uint32_t)(np * 16 * PITCHB + ks * 32));
#pragma unroll
            for (int ma = 0; ma < 4; ma++)
#pragma unroll
                for (int np = 0; np < 4; np++) {
                    mma_bf16(acc[ma][2*np],   a[ma], &bb[np][0]);
                    mma_bf16(acc[ma][2*np+1], a[ma], &bb[np][2]);
                }
        }
        __syncthreads();
    }

    // Epilogue
#pragma unroll
    for (int ma = 0; ma < 4; ma++) {
        int row0 = m0 + warp_m + ma * 16 + g;
#pragma unroll
        for (int na = 0; na < 8; na++) {
            int col = n0 + warp_n + na * 8 + tig * 2;
            if (col < N) {
                float v0 = acc[ma][na][0], v1 = acc[ma][na][1];
                float v2 = acc[ma][na][2], v3 = acc[ma][na][3];
                if (MODE == 0) {
                    __nv_bfloat16* Cb = (__nv_bfloat16*)Cv;
                    *(__nv_bfloat162*)&Cb[(size_t)row0 * ldc + col] =
                        __floats2bfloat162_rn(v0, v1);
                    *(__nv_bfloat162*)&Cb[(size_t)(row0 + 8) * ldc + col] =
                        __floats2bfloat162_rn(v2, v3);
                } else if (MODE == 1) {
                    __nv_bfloat16* Cb = (__nv_bfloat16*)Cv;
                    v0 = softplus_f(v0 + ep[col]);  v1 = softplus_f(v1 + ep[col+1]);
                    v2 = softplus_f(v2 + ep[col]);  v3 = softplus_f(v3 + ep[col+1]);
                    *(__nv_bfloat162*)&Cb[(size_t)row0 * ldc + col] =
                        __floats2bfloat162_rn(v0, v1);
                    *(__nv_bfloat162*)&Cb[(size_t)(row0 + 8) * ldc + col] =
                        __floats2bfloat162_rn(v2, v3);
                } else {
                    float* C = (float*)Cv + (size_t)blockIdx.z * zstride;
                    if (MODE == 2) {
                        const float2 e0 = *(const float2*)&ep[(size_t)row0 * ldc + col];
                        const float2 e1 = *(const float2*)&ep[(size_t)(row0+8) * ldc + col];
                        v0 += e0.x; v1 += e0.y; v2 += e1.x; v3 += e1.y;
                    }
                    *(float2*)&C[(size_t)row0 * ldc + col]       = make_float2(v0, v1);
                    *(float2*)&C[(size_t)(row0 + 8) * ldc + col] = make_float2(v2, v3);
                }
            }
        }
    }
}

// ===========================================================================
// Single fused fp32 -> bf16 weight conversion (4 segments, 1 launch)
// ===========================================================================
#define S0 (2*DI*DM/4)
#define S1 (XPROJ_N*DI/4)
#define S2 (DI*DR/4)
#define S3 (DM*DI/4)
__global__ void __launch_bounds__(256) cvt_all_kernel(
    const float4* __restrict__ w_in,  __nv_bfloat162* __restrict__ o_in,
    const float4* __restrict__ w_xp,  __nv_bfloat162* __restrict__ o_xp,
    const float4* __restrict__ w_dt,  __nv_bfloat162* __restrict__ o_dt,
    const float4* __restrict__ w_out, __nv_bfloat162* __restrict__ o_out)
{
    int i = blockIdx.x * 256 + threadIdx.x;
    const float4* src; __nv_bfloat162* dst; int j;
    if      (i < S0)            { src = w_in;  dst = o_in;  j = i; }
    else if (i < S0+S1)         { src = w_xp;  dst = o_xp;  j = i - S0; }
    else if (i < S0+S1+S2)      { src = w_dt;  dst = o_dt;  j = i - S0 - S1; }
    else if (i < S0+S1+S2+S3)   { src = w_out; dst = o_out; j = i - S0 - S1 - S2; }
    else return;
    float4 v = src[j];
    dst[2*j]   = __floats2bfloat162_rn(v.x, v.y);
    dst[2*j+1] = __floats2bfloat162_rn(v.z, v.w);
}

// ===========================================================================
// Split-K reduction for x_dbl; also emits bf16 dt_r slice (cols 0..47)
// ===========================================================================
__global__ void __launch_bounds__(256) reduce_ksplit_kernel(
    const float* __restrict__ part, float* __restrict__ o,
    __nv_bfloat16* __restrict__ dtr_bf)
{
    int i = blockIdx.x * 256 + threadIdx.x;
    float s = 0.f;
#pragma unroll
    for (int z = 0; z < KSPLIT; z++) s += part[(size_t)z * PART_STRIDE + i];
    o[i] = s;
    int row = i / XPROJ_N, col = i - row * XPROJ_N;
    if (col < DR) dtr_bf[row * DR + col] = __float2bfloat16(s);
}

// ===========================================================================
// Block reduce (256 threads)
// ===========================================================================
__device__ __forceinline__ float blockReduce256(float v, float* sh) {
    __syncthreads();
    int lane = threadIdx.x & 31, w = threadIdx.x >> 5;
#pragma unroll
    for (int o = 16; o; o >>= 1) v += __shfl_xor_sync(0xffffffffu, v, o);
    if (lane == 0) sh[w] = v;
    __syncthreads();
    float r = sh[0];
#pragma unroll
    for (int i = 1; i < 8; i++) r += sh[i];
    return r;
}

// ---------------------------------------------------------------------------
// LayerNorm -> bf16 h
// ---------------------------------------------------------------------------
__global__ void __launch_bounds__(256) ln_kernel(
    const float* __restrict__ x, const float* __restrict__ g,
    const float* __restrict__ bta, __nv_bfloat16* __restrict__ h)
{
    __shared__ float sh[8];
    int row = blockIdx.x;
    int tid = threadIdx.x;
    const float* xr = x + (size_t)row * DM;
    float v[3]; float sum = 0.f;
#pragma unroll
    for (int i = 0; i < 3; i++) { v[i] = xr[tid + i*256]; sum += v[i]; }
    sum = blockReduce256(sum, sh);
    float mu = sum * (1.f/768.f);
    float q = 0.f;
#pragma unroll
    for (int i = 0; i < 3; i++) { float d = v[i]-mu; q += d*d; }
    q = blockReduce256(q, sh);
    float rs = rsqrtf(q * (1.f/768.f) + 1e-5f);
    __nv_bfloat16* hr = h + (size_t)row * DM;
#pragma unroll
    for (int i = 0; i < 3; i++) {
        int c = tid + i*256;
        hr[c] = __float2bfloat16((v[i]-mu) * rs * g[c] + bta[c]);
    }
}

// ---------------------------------------------------------------------------
// Depthwise causal conv (width 4) + bias + SiLU.
// One thread: 8 channels x 4 timesteps (uint4 = 8 bf16 per row load).
// ---------------------------------------------------------------------------
__global__ void __launch_bounds__(256) conv_silu_kernel(
    const __nv_bfloat16* __restrict__ xz, const float* __restrict__ w,
    const float* __restrict__ b, __nv_bfloat16* __restrict__ xc_bf)
{
    const int idx = blockIdx.x * 256 + threadIdx.x;  // over (TOK/4)*(DI/8)
    const int d8 = idx % (DI/8);
    const int t4 = (idx / (DI/8)) % (TT_SEQ/4);
    const int bb = idx / ((DI/8) * (TT_SEQ/4));
    const int d  = d8 * 8;
    const int tbase = t4 * 4;
    const __nv_bfloat16* xs = xz + (size_t)bb * TT_SEQ * (2*DI);

    // weights: w[c][k], c = d..d+7
    float wk[8][4];
#pragma unroll
    for (int c = 0; c < 8; c++) {
        float4 wc = ((const float4*)w)[d + c];
        wk[c][0] = wc.x; wk[c][1] = wc.y; wk[c][2] = wc.z; wk[c][3] = wc.w;
    }
    float bias[8];
    {
        float4 b0 = *(const float4*)&b[d];
        float4 b1 = *(const float4*)&b[d+4];
        bias[0]=b0.x; bias[1]=b0.y; bias[2]=b0.z; bias[3]=b0.w;
        bias[4]=b1.x; bias[5]=b1.y; bias[6]=b1.z; bias[7]=b1.w;
    }

    // input rows tbase-3 .. tbase+3 (7 rows x 8 channels)
    float xv[7][8];
#pragma unroll
    for (int r = 0; r < 7; r++) {
        int tt = tbase - 3 + r;
        if (tt >= 0) {
            uint4 u = *(const uint4*)&xs[(size_t)tt * (2*DI) + d];
            const __nv_bfloat162* p2 = (const __nv_bfloat162*)&u;
#pragma unroll
            for (int c2 = 0; c2 < 4; c2++) {
                float2 f = __bfloat1622float2(p2[c2]);
                xv[r][2*c2]   = f.x;
                xv[r][2*c2+1] = f.y;
            }
        } else {
#pragma unroll
            for (int c = 0; c < 8; c++) xv[r][c] = 0.f;
        }
    }

#pragma unroll
    for (int ti = 0; ti < 4; ti++) {
        __nv_bfloat162 ov[4];
#pragma unroll
        for (int c2 = 0; c2 < 4; c2++) {
            float a0 = bias[2*c2], a1 = bias[2*c2+1];
#pragma unroll
            for (int k = 0; k < 4; k++) {
                a0 = fmaf(wk[2*c2][k],   xv[ti+k][2*c2],   a0);
                a1 = fmaf(wk[2*c2+1][k], xv[ti+k][2*c2+1], a1);
            }
            ov[c2] = __floats2bfloat162_rn(silu_f(a0), silu_f(a1));
        }
        *(uint4*)&xc_bf[(size_t)(bb * TT_SEQ + tbase + ti) * DI + d] =
            *(const uint4*)ov;
    }
}

// ---------------------------------------------------------------------------
// Selective scan (16 channels x 16 states per block), deferred reduction.
// All streaming operands bf16; math fp32.
// ---------------------------------------------------------------------------
__global__ void __launch_bounds__(256) scan_kernel(
    const __nv_bfloat16* __restrict__ dt, const __nv_bfloat16* __restrict__ xc,
    const __nv_bfloat16* __restrict__ xz, const float* __restrict__ xdbl,
    const float* __restrict__ A_log, const float* __restrict__ Dp,
    __nv_bfloat16* __restrict__ y)
{
    constexpr int CH = 32;
    __shared__ float dt_s[CH][16], xc_s[CH][16], z_s[CH][16];
    __shared__ float B_s[CH][16], C_s[CH][16];
    __shared__ float p_s[CH][16][16];
    __shared__ float Dp_s[16];

    const int b  = blockIdx.y;
    const int d0 = blockIdx.x * 16;
    const int tid = threadIdx.x;
    const int n  = tid & 15;
    const int dl = tid >> 4;
    const int d  = d0 + dl;

    const float A_dn = -__expf(A_log[d * DS + n]);
    if (tid < 16) Dp_s[tid] = Dp[d0 + tid];
    float s = 0.f;
    const size_t base = (size_t)b * TT_SEQ;

    for (int t0 = 0; t0 < TT_SEQ; t0 += CH) {
#pragma unroll
        for (int i = 0; i < 2; i++) {
            int e = tid + i*256; int tt = e >> 4, j = e & 15;
            size_t row = base + t0 + tt;
            dt_s[tt][j] = __bfloat162float(dt[row * DI + d0 + j]);
            xc_s[tt][j] = __bfloat162float(xc[row * DI + d0 + j]);
            z_s[tt][j]  = __bfloat162float(xz[row * (2*DI) + DI + d0 + j]);
            B_s[tt][j]  = xdbl[row * XPROJ_N + DR + j];
            C_s[tt][j]  = xdbl[row * XPROJ_N + DR + DS + j];
        }
        __syncthreads();
#pragma unroll 4
        for (int t = 0; t < CH; t++) {
            float dtv = dt_s[t][dl];
            float xcv = xc_s[t][dl];
            float dA  = __expf(A_dn * dtv);
            s = fmaf(dA, s, dtv * xcv * B_s[t][n]);
            p_s[t][dl][n] = s * C_s[t][n];
        }
        __syncthreads();
#pragma unroll
        for (int i = 0; i < 2; i++) {
            int e = tid + i*256; int tt = e >> 4, ch = e & 15;
            const float4* pp = (const float4*)p_s[tt][ch];
            float4 q0 = pp[0], q1 = pp[1], q2 = pp[2], q3 = pp[3];
            float sum = ((q0.x+q0.y)+(q0.z+q0.w)) + ((q1.x+q1.y)+(q1.z+q1.w))
                      + ((q2.x+q2.y)+(q2.z+q2.w)) + ((q3.x+q3.y)+(q3.z+q3.w));
            float xcv = xc_s[tt][ch];
            float zv  = z_s[tt][ch];
            y[(base + t0 + tt) * DI + d0 + ch] =
                __float2bfloat16((sum + Dp_s[ch] * xcv) * silu_f(zv));
        }
        __syncthreads();
    }
}

// ---------------------------------------------------------------------------
// Launch
// ---------------------------------------------------------------------------
extern "C" void kernel_launch(void* const* d_in, const int* in_sizes, int n_in,
                              void* d_out, int out_size)
{
    const float* x      = (const float*)d_in[0];
    const float* ln_g   = (const float*)d_in[1];
    const float* ln_b   = (const float*)d_in[2];
    const float* W_in   = (const float*)d_in[3];
    const float* conv_w = (const float*)d_in[4];
    const float* conv_b = (const float*)d_in[5];
    const float* W_xprj = (const float*)d_in[6];
    const float* W_dt   = (const float*)d_in[7];
    const float* b_dt   = (const float*)d_in[8];
    const float* A_log  = (const float*)d_in[9];
    const float* Dp     = (const float*)d_in[10];
    const float* W_out  = (const float*)d_in[11];
    float* out = (float*)d_out;

    float *xdbl, *xdblp;
    __nv_bfloat16 *xz, *dt_bf, *h_bf, *xc_bf, *dtr_bf, *y_bf;
    __nv_bfloat16 *Win_bf, *Wxp_bf, *Wdt_bf, *Wout_bf;
    cudaGetSymbolAddress((void**)&xz,      g_xz);
    cudaGetSymbolAddress((void**)&xdbl,    g_xdbl);
    cudaGetSymbolAddress((void**)&xdblp,   g_xdbl_part);
    cudaGetSymbolAddress((void**)&dt_bf,   g_dt_bf);
    cudaGetSymbolAddress((void**)&h_bf,    g_h_bf);
    cudaGetSymbolAddress((void**)&xc_bf,   g_xc_bf);
    cudaGetSymbolAddress((void**)&dtr_bf,  g_dtr_bf);
    cudaGetSymbolAddress((void**)&y_bf,    g_y_bf);
    cudaGetSymbolAddress((void**)&Win_bf,  g_Win_bf);
    cudaGetSymbolAddress((void**)&Wxp_bf,  g_Wxp_bf);
    cudaGetSymbolAddress((void**)&Wdt_bf,  g_Wdt_bf);
    cudaGetSymbolAddress((void**)&Wout_bf, g_Wout_bf);

    cudaFuncSetAttribute(gemm_mma_kernel<0>,
        cudaFuncAttributeMaxDynamicSharedMemorySize, GEMM_SMEM_BYTES);
    cudaFuncSetAttribute(gemm_mma_kernel<1>,
        cudaFuncAttributeMaxDynamicSharedMemorySize, GEMM_SMEM_BYTES);
    cudaFuncSetAttribute(gemm_mma_kernel<2>,
        cudaFuncAttributeMaxDynamicSharedMemorySize, GEMM_SMEM_BYTES);
    cudaFuncSetAttribute(gemm_mma_kernel<3>,
        cudaFuncAttributeMaxDynamicSharedMemorySize, GEMM_SMEM_BYTES);

    // 0. weight conversions (single launch)
    cvt_all_kernel<<<(S0+S1+S2+S3 + 255)/256, 256>>>(
        (const float4*)W_in,  (__nv_bfloat162*)Win_bf,
        (const float4*)W_xprj,(__nv_bfloat162*)Wxp_bf,
        (const float4*)W_dt,  (__nv_bfloat162*)Wdt_bf,
        (const float4*)W_out, (__nv_bfloat162*)Wout_bf);

    // 1. LayerNorm -> bf16
    ln_kernel<<<TOK, 256>>>(x, ln_g, ln_b, h_bf);

    // 2. xz = h @ W_in^T  (2048 x 3072 x 768), bf16 out
    gemm_mma_kernel<0><<<dim3(2*DI/128, TOK/128, 1), 128, GEMM_SMEM_BYTES>>>(
        h_bf, DM, Win_bf, DM, xz, 2*DI, nullptr, 2*DI, DM, DM, 0);

    // 3. depthwise conv + silu -> xc (bf16)
    conv_silu_kernel<<<(TOK/4)*(DI/8)/256, 256>>>(xz, conv_w, conv_b, xc_bf);

    // 4. x_dbl = xc @ W_xproj^T  (2048 x 80 x 1536), split-K=8 -> reduce
    gemm_mma_kernel<3><<<dim3(1, TOK/128, KSPLIT), 128, GEMM_SMEM_BYTES>>>(
        xc_bf, DI, Wxp_bf, DI, xdblp, XPROJ_N, nullptr, XPROJ_N, DI, DI/KSPLIT,
        (size_t)PART_STRIDE);
    reduce_ksplit_kernel<<<(TOK*XPROJ_N)/256, 256>>>(xdblp, xdbl, dtr_bf);

    // 5. dt = softplus(dt_r @ W_dt^T + b_dt)  (2048 x 1536 x 48), bf16 out
    gemm_mma_kernel<1><<<dim3(DI/128, TOK/128, 1), 128, GEMM_SMEM_BYTES>>>(
        dtr_bf, DR, Wdt_bf, DR, dt_bf, DI, b_dt, DI, DR, DR, 0);

    // 6. selective scan -> y (gated, bf16)
    scan_kernel<<<dim3(DI/16, BB), 256>>>(dt_bf, xc_bf, xz, xdbl, A_log, Dp, y_bf);

    // 7. out = x + y @ W_out^T  (2048 x 768 x 1536)
    gemm_mma_kernel<2><<<dim3(DM/128, TOK/128, 1), 128, GEMM_SMEM_BYTES>>>(
        y_bf, DI, Wout_bf, DI, out, DM, x, DM, DI, DI, 0);
}

// round 10
// speedup vs baseline: 1.0635x; 1.0635x over previous
#include <cuda_runtime.h>
#include <cuda_bf16.h>
#include <math.h>
#include <stdint.h>

// Shapes (fixed by the problem)
#define BB      2
#define TT_SEQ  1024
#define DM      768
#define DI      1536        // D_INNER
#define DS      16          // D_STATE
#define DR      48          // DT_RANK
#define TOK     (BB*TT_SEQ) // 2048
#define XPROJ_N (DR + 2*DS) // 80
#define KSPLIT  8
#define PART_STRIDE (TOK * XPROJ_N)   // 163840

// -------- device scratch (no allocs allowed) --------
__device__ __nv_bfloat16  g_xz       [TOK * 2 * DI];
__device__ float          g_xdbl     [TOK * XPROJ_N];
__device__ float          g_xdbl_part[KSPLIT * PART_STRIDE];
__device__ __nv_bfloat16  g_dt_bf    [TOK * DI];
__device__ __nv_bfloat16  g_h_bf     [TOK * DM];
__device__ __nv_bfloat16  g_xc_bf    [TOK * DI];
__device__ __nv_bfloat16  g_dtr_bf   [TOK * DR];
__device__ __nv_bfloat16  g_y_bf     [TOK * DI];
__device__ __nv_bfloat16  g_Win_bf   [2 * DI * DM];
__device__ __nv_bfloat16  g_Wxp_bf   [XPROJ_N * DI];
__device__ __nv_bfloat16  g_Wdt_bf   [DI * DR];
__device__ __nv_bfloat16  g_Wout_bf  [DM * DI];

// ===========================================================================
// Helpers
// ===========================================================================
__device__ __forceinline__ void cp16(uint32_t dst, const void* src, int bytes) {
    asm volatile("cp.async.cg.shared.global [%0], [%1], 16, %2;"
                 :: "r"(dst), "l"(src), "r"(bytes) : "memory");
}
#define CP_COMMIT() asm volatile("cp.async.commit_group;" ::: "memory")
#define CP_WAIT(n)  asm volatile("cp.async.wait_group %0;" :: "n"(n) : "memory")

__device__ __forceinline__ uint32_t smem_u32(const void* p) {
    uint32_t a;
    asm("{ .reg .u64 t; cvta.to.shared.u64 t, %1; cvt.u32.u64 %0, t; }"
        : "=r"(a) : "l"(p));
    return a;
}

__device__ __forceinline__ void mma_bf16(float* c, const uint32_t* a, const uint32_t* b) {
    asm volatile(
        "mma.sync.aligned.m16n8k16.row.col.f32.bf16.bf16.f32 "
        "{%0,%1,%2,%3}, {%4,%5,%6,%7}, {%8,%9}, {%0,%1,%2,%3};"
        : "+f"(c[0]), "+f"(c[1]), "+f"(c[2]), "+f"(c[3])
        : "r"(a[0]), "r"(a[1]), "r"(a[2]), "r"(a[3]), "r"(b[0]), "r"(b[1]));
}

__device__ __forceinline__ void ldsm_x4(uint32_t* r, uint32_t addr) {
    asm volatile("ldmatrix.sync.aligned.m8n8.x4.shared.b16 {%0,%1,%2,%3}, [%4];"
        : "=r"(r[0]), "=r"(r[1]), "=r"(r[2]), "=r"(r[3]) : "r"(addr));
}

__device__ __forceinline__ float softplus_f(float v) {
    return (v > 20.f) ? v : __logf(1.f + __expf(v));
}
__device__ __forceinline__ float silu_f(float v) {
    return __fdividef(v, 1.f + __expf(-v));
}

// ===========================================================================
// bf16 mma.sync GEMM, ldmatrix fragments, 3-stage cp.async pipeline.
// C = A(M x K, lda) * B(N x K, ldb)^T. Block tile 64x128, BK=32,
// 128 threads = 4 warps (2Mx2N), warp tile 32x64. Smem rows 80B.
// MODE 0: store bf16. MODE 1: softplus(+ep[col]) -> bf16.
// MODE 2: +ep[row*ldc+col] fp32. MODE 3: store fp32 (split-K partials).
// ===========================================================================
#define PITCHB 80
#define TILE_A_B (64 * PITCHB)               // 5120
#define TILE_B_B (128 * PITCHB)              // 10240
#define BUF_B  (TILE_A_B + TILE_B_B)         // 15360
#define NSTAGE 3
#define GEMM_SMEM_BYTES (NSTAGE * BUF_B)     // 46080

template<int MODE>
__global__ void __launch_bounds__(128, 3) gemm_mma_kernel(
    const __nv_bfloat16* __restrict__ A, int lda,
    const __nv_bfloat16* __restrict__ B, int ldb,
    void* __restrict__ Cv, int ldc,
    const float* __restrict__ ep,
    int N, int Ktotal, int ksplit, size_t zstride)
{
    extern __shared__ char smem[];
    const int tid = threadIdx.x;
    const int wid = tid >> 5, lid = tid & 31;
    const int g = lid >> 2, tig = lid & 3;
    const int warp_m = (wid & 1) * 32;
    const int warp_n = (wid >> 1) * 64;
    const int m0 = blockIdx.y * 64;
    const int n0 = blockIdx.x * 128;
    const int kbeg = blockIdx.z * ksplit;
    const int kend = min(kbeg + ksplit, Ktotal);

    const uint32_t sbase = smem_u32(smem);
    const uint32_t aoff = (uint32_t)((warp_m + (lid & 15)) * PITCHB + ((lid >> 4) << 4));
    const uint32_t boff = (uint32_t)((warp_n + (lid & 7) + ((lid >> 4) & 1) * 8) * PITCHB
                                     + ((lid >> 3) & 1) * 16);

    float acc[2][8][4];
#pragma unroll
    for (int i = 0; i < 2; i++)
#pragma unroll
        for (int j = 0; j < 8; j++)
#pragma unroll
            for (int q = 0; q < 4; q++) acc[i][j][q] = 0.f;

    const int NT = (kend - kbeg + 31) >> 5;

    // 64 A rows (256 cp16) + 128 B rows (512 cp16) = 768 cp16 / 128 thr = 6 each
    auto load_tiles = [&](int it) {
        const int buf = it % NSTAGE;
        const int k0 = kbeg + it * 32;
        const uint32_t sA = sbase + (uint32_t)buf * BUF_B;
        const uint32_t sB = sA + TILE_A_B;
#pragma unroll
        for (int j = 0; j < 6; j++) {
            int idx = tid + j * 128;           // 0..767
            int c8 = (idx & 3) * 8;
            int kk = k0 + c8;
            int bytes = min(max(kend - kk, 0), 8) * 2;
            int ksafe = bytes ? kk : k0;
            if (idx < 256) {
                int r = idx >> 2;              // A row 0..63
                cp16(sA + (uint32_t)(r * PITCHB + c8 * 2),
                     A + (size_t)(m0 + r) * lda + ksafe, bytes);
            } else {
                int r = (idx - 256) >> 2;      // B row 0..127
                int nr = n0 + r;
                int bytesB = (nr < N) ? bytes : 0;
                cp16(sB + (uint32_t)(r * PITCHB + c8 * 2),
                     B + (size_t)((nr < N) ? nr : 0) * ldb + ksafe, bytesB);
            }
        }
        CP_COMMIT();
    };

    load_tiles(0);
    if (NT > 1) load_tiles(1);

    for (int it = 0; it < NT; it++) {
        if (it + 2 < NT) { load_tiles(it + 2); CP_WAIT(2); }
        else if (it + 1 < NT) { CP_WAIT(1); }
        else { CP_WAIT(0); }
        __syncthreads();

        const uint32_t sA = sbase + (uint32_t)(it % NSTAGE) * BUF_B;
        const uint32_t a_base = sA + aoff;
        const uint32_t b_base = sA + TILE_A_B + boff;
#pragma unroll
        for (int ks = 0; ks < 2; ks++) {
            uint32_t a[2][4], bb[4][4];
#pragma unroll
            for (int ma = 0; ma < 2; ma++)
                ldsm_x4(a[ma], a_base + (uint32_t)(ma * 16 * PITCHB + ks * 32));
#pragma unroll
            for (int np = 0; np < 4; np++)
                ldsm_x4(bb[np], b_base + (uint32_t)(np * 16 * PITCHB + ks * 32));
#pragma unroll
            for (int ma = 0; ma < 2; ma++)
#pragma unroll
                for (int np = 0; np < 4; np++) {
                    mma_bf16(acc[ma][2*np],   a[ma], &bb[np][0]);
                    mma_bf16(acc[ma][2*np+1], a[ma], &bb[np][2]);
                }
        }
        __syncthreads();
    }

    // Epilogue
#pragma unroll
    for (int ma = 0; ma < 2; ma++) {
        int row0 = m0 + warp_m + ma * 16 + g;
#pragma unroll
        for (int na = 0; na < 8; na++) {
            int col = n0 + warp_n + na * 8 + tig * 2;
            if (col < N) {
                float v0 = acc[ma][na][0], v1 = acc[ma][na][1];
                float v2 = acc[ma][na][2], v3 = acc[ma][na][3];
                if (MODE == 0) {
                    __nv_bfloat16* Cb = (__nv_bfloat16*)Cv;
                    *(__nv_bfloat162*)&Cb[(size_t)row0 * ldc + col] =
                        __floats2bfloat162_rn(v0, v1);
                    *(__nv_bfloat162*)&Cb[(size_t)(row0 + 8) * ldc + col] =
                        __floats2bfloat162_rn(v2, v3);
                } else if (MODE == 1) {
                    __nv_bfloat16* Cb = (__nv_bfloat16*)Cv;
                    v0 = softplus_f(v0 + ep[col]);  v1 = softplus_f(v1 + ep[col+1]);
                    v2 = softplus_f(v2 + ep[col]);  v3 = softplus_f(v3 + ep[col+1]);
                    *(__nv_bfloat162*)&Cb[(size_t)row0 * ldc + col] =
                        __floats2bfloat162_rn(v0, v1);
                    *(__nv_bfloat162*)&Cb[(size_t)(row0 + 8) * ldc + col] =
                        __floats2bfloat162_rn(v2, v3);
                } else {
                    float* C = (float*)Cv + (size_t)blockIdx.z * zstride;
                    if (MODE == 2) {
                        const float2 e0 = *(const float2*)&ep[(size_t)row0 * ldc + col];
                        const float2 e1 = *(const float2*)&ep[(size_t)(row0+8) * ldc + col];
                        v0 += e0.x; v1 += e0.y; v2 += e1.x; v3 += e1.y;
                    }
                    *(float2*)&C[(size_t)row0 * ldc + col]       = make_float2(v0, v1);
                    *(float2*)&C[(size_t)(row0 + 8) * ldc + col] = make_float2(v2, v3);
                }
            }
        }
    }
}

// ===========================================================================
// Single fused fp32 -> bf16 weight conversion (4 segments, 1 launch)
// ===========================================================================
#define S0 (2*DI*DM/4)
#define S1 (XPROJ_N*DI/4)
#define S2 (DI*DR/4)
#define S3 (DM*DI/4)
__global__ void __launch_bounds__(256) cvt_all_kernel(
    const float4* __restrict__ w_in,  __nv_bfloat162* __restrict__ o_in,
    const float4* __restrict__ w_xp,  __nv_bfloat162* __restrict__ o_xp,
    const float4* __restrict__ w_dt,  __nv_bfloat162* __restrict__ o_dt,
    const float4* __restrict__ w_out, __nv_bfloat162* __restrict__ o_out)
{
    int i = blockIdx.x * 256 + threadIdx.x;
    const float4* src; __nv_bfloat162* dst; int j;
    if      (i < S0)            { src = w_in;  dst = o_in;  j = i; }
    else if (i < S0+S1)         { src = w_xp;  dst = o_xp;  j = i - S0; }
    else if (i < S0+S1+S2)      { src = w_dt;  dst = o_dt;  j = i - S0 - S1; }
    else if (i < S0+S1+S2+S3)   { src = w_out; dst = o_out; j = i - S0 - S1 - S2; }
    else return;
    float4 v = src[j];
    dst[2*j]   = __floats2bfloat162_rn(v.x, v.y);
    dst[2*j+1] = __floats2bfloat162_rn(v.z, v.w);
}

// ===========================================================================
// Split-K reduction for x_dbl; also emits bf16 dt_r slice (cols 0..47)
// ===========================================================================
__global__ void __launch_bounds__(256) reduce_ksplit_kernel(
    const float* __restrict__ part, float* __restrict__ o,
    __nv_bfloat16* __restrict__ dtr_bf)
{
    int i = blockIdx.x * 256 + threadIdx.x;
    float s = 0.f;
#pragma unroll
    for (int z = 0; z < KSPLIT; z++) s += part[(size_t)z * PART_STRIDE + i];
    o[i] = s;
    int row = i / XPROJ_N, col = i - row * XPROJ_N;
    if (col < DR) dtr_bf[row * DR + col] = __float2bfloat16(s);
}

// ===========================================================================
// Block reduce (256 threads)
// ===========================================================================
__device__ __forceinline__ float blockReduce256(float v, float* sh) {
    __syncthreads();
    int lane = threadIdx.x & 31, w = threadIdx.x >> 5;
#pragma unroll
    for (int o = 16; o; o >>= 1) v += __shfl_xor_sync(0xffffffffu, v, o);
    if (lane == 0) sh[w] = v;
    __syncthreads();
    float r = sh[0];
#pragma unroll
    for (int i = 1; i < 8; i++) r += sh[i];
    return r;
}

// ---------------------------------------------------------------------------
// LayerNorm -> bf16 h
// ---------------------------------------------------------------------------
__global__ void __launch_bounds__(256) ln_kernel(
    const float* __restrict__ x, const float* __restrict__ g,
    const float* __restrict__ bta, __nv_bfloat16* __restrict__ h)
{
    __shared__ float sh[8];
    int row = blockIdx.x;
    int tid = threadIdx.x;
    const float* xr = x + (size_t)row * DM;
    float v[3]; float sum = 0.f;
#pragma unroll
    for (int i = 0; i < 3; i++) { v[i] = xr[tid + i*256]; sum += v[i]; }
    sum = blockReduce256(sum, sh);
    float mu = sum * (1.f/768.f);
    float q = 0.f;
#pragma unroll
    for (int i = 0; i < 3; i++) { float d = v[i]-mu; q += d*d; }
    q = blockReduce256(q, sh);
    float rs = rsqrtf(q * (1.f/768.f) + 1e-5f);
    __nv_bfloat16* hr = h + (size_t)row * DM;
#pragma unroll
    for (int i = 0; i < 3; i++) {
        int c = tid + i*256;
        hr[c] = __float2bfloat16((v[i]-mu) * rs * g[c] + bta[c]);
    }
}

// ---------------------------------------------------------------------------
// Depthwise causal conv (width 4) + bias + SiLU.
// One thread: 8 channels x 2 timesteps (uint4 = 8 bf16 per row load).
// ---------------------------------------------------------------------------
__global__ void __launch_bounds__(256) conv_silu_kernel(
    const __nv_bfloat16* __restrict__ xz, const float* __restrict__ w,
    const float* __restrict__ b, __nv_bfloat16* __restrict__ xc_bf)
{
    const int idx = blockIdx.x * 256 + threadIdx.x;  // over (TOK/2)*(DI/8)
    const int d8 = idx % (DI/8);
    const int t2 = (idx / (DI/8)) % (TT_SEQ/2);
    const int bb = idx / ((DI/8) * (TT_SEQ/2));
    const int d  = d8 * 8;
    const int tbase = t2 * 2;
    const __nv_bfloat16* xs = xz + (size_t)bb * TT_SEQ * (2*DI);

    float wk[8][4];
#pragma unroll
    for (int c = 0; c < 8; c++) {
        float4 wc = ((const float4*)w)[d + c];
        wk[c][0] = wc.x; wk[c][1] = wc.y; wk[c][2] = wc.z; wk[c][3] = wc.w;
    }
    float bias[8];
    {
        float4 b0 = *(const float4*)&b[d];
        float4 b1 = *(const float4*)&b[d+4];
        bias[0]=b0.x; bias[1]=b0.y; bias[2]=b0.z; bias[3]=b0.w;
        bias[4]=b1.x; bias[5]=b1.y; bias[6]=b1.z; bias[7]=b1.w;
    }

    // input rows tbase-3 .. tbase+1 (5 rows x 8 channels)
    float xv[5][8];
#pragma unroll
    for (int r = 0; r < 5; r++) {
        int tt = tbase - 3 + r;
        if (tt >= 0) {
            uint4 u = *(const uint4*)&xs[(size_t)tt * (2*DI) + d];
            const __nv_bfloat162* p2 = (const __nv_bfloat162*)&u;
#pragma unroll
            for (int c2 = 0; c2 < 4; c2++) {
                float2 f = __bfloat1622float2(p2[c2]);
                xv[r][2*c2]   = f.x;
                xv[r][2*c2+1] = f.y;
            }
        } else {
#pragma unroll
            for (int c = 0; c < 8; c++) xv[r][c] = 0.f;
        }
    }

#pragma unroll
    for (int ti = 0; ti < 2; ti++) {
        __nv_bfloat162 ov[4];
#pragma unroll
        for (int c2 = 0; c2 < 4; c2++) {
            float a0 = bias[2*c2], a1 = bias[2*c2+1];
#pragma unroll
            for (int k = 0; k < 4; k++) {
                a0 = fmaf(wk[2*c2][k],   xv[ti+k][2*c2],   a0);
                a1 = fmaf(wk[2*c2+1][k], xv[ti+k][2*c2+1], a1);
            }
            ov[c2] = __floats2bfloat162_rn(silu_f(a0), silu_f(a1));
        }
        *(uint4*)&xc_bf[(size_t)(bb * TT_SEQ + tbase + ti) * DI + d] =
            *(const uint4*)ov;
    }
}

// ---------------------------------------------------------------------------
// Selective scan (16 channels x 16 states per block), deferred reduction.
// All streaming operands bf16; math fp32.
// ---------------------------------------------------------------------------
__global__ void __launch_bounds__(256) scan_kernel(
    const __nv_bfloat16* __restrict__ dt, const __nv_bfloat16* __restrict__ xc,
    const __nv_bfloat16* __restrict__ xz, const float* __restrict__ xdbl,
    const float* __restrict__ A_log, const float* __restrict__ Dp,
    __nv_bfloat16* __restrict__ y)
{
    constexpr int CH = 32;
    __shared__ float dt_s[CH][16], xc_s[CH][16], z_s[CH][16];
    __shared__ float B_s[CH][16], C_s[CH][16];
    __shared__ float p_s[CH][16][16];
    __shared__ float Dp_s[16];

    const int b  = blockIdx.y;
    const int d0 = blockIdx.x * 16;
    const int tid = threadIdx.x;
    const int n  = tid & 15;
    const int dl = tid >> 4;
    const int d  = d0 + dl;

    const float A_dn = -__expf(A_log[d * DS + n]);
    if (tid < 16) Dp_s[tid] = Dp[d0 + tid];
    float s = 0.f;
    const size_t base = (size_t)b * TT_SEQ;

    for (int t0 = 0; t0 < TT_SEQ; t0 += CH) {
#pragma unroll
        for (int i = 0; i < 2; i++) {
            int e = tid + i*256; int tt = e >> 4, j = e & 15;
            size_t row = base + t0 + tt;
            dt_s[tt][j] = __bfloat162float(dt[row * DI + d0 + j]);
            xc_s[tt][j] = __bfloat162float(xc[row * DI + d0 + j]);
            z_s[tt][j]  = __bfloat162float(xz[row * (2*DI) + DI + d0 + j]);
            B_s[tt][j]  = xdbl[row * XPROJ_N + DR + j];
            C_s[tt][j]  = xdbl[row * XPROJ_N + DR + DS + j];
        }
        __syncthreads();
#pragma unroll 4
        for (int t = 0; t < CH; t++) {
            float dtv = dt_s[t][dl];
            float xcv = xc_s[t][dl];
            float dA  = __expf(A_dn * dtv);
            s = fmaf(dA, s, dtv * xcv * B_s[t][n]);
            p_s[t][dl][n] = s * C_s[t][n];
        }
        __syncthreads();
#pragma unroll
        for (int i = 0; i < 2; i++) {
            int e = tid + i*256; int tt = e >> 4, ch = e & 15;
            const float4* pp = (const float4*)p_s[tt][ch];
            float4 q0 = pp[0], q1 = pp[1], q2 = pp[2], q3 = pp[3];
            float sum = ((q0.x+q0.y)+(q0.z+q0.w)) + ((q1.x+q1.y)+(q1.z+q1.w))
                      + ((q2.x+q2.y)+(q2.z+q2.w)) + ((q3.x+q3.y)+(q3.z+q3.w));
            float xcv = xc_s[tt][ch];
            float zv  = z_s[tt][ch];
            y[(base + t0 + tt) * DI + d0 + ch] =
                __float2bfloat16((sum + Dp_s[ch] * xcv) * silu_f(zv));
        }
        __syncthreads();
    }
}

// ---------------------------------------------------------------------------
// Launch
// ---------------------------------------------------------------------------
extern "C" void kernel_launch(void* const* d_in, const int* in_sizes, int n_in,
                              void* d_out, int out_size)
{
    const float* x      = (const float*)d_in[0];
    const float* ln_g   = (const float*)d_in[1];
    const float* ln_b   = (const float*)d_in[2];
    const float* W_in   = (const float*)d_in[3];
    const float* conv_w = (const float*)d_in[4];
    const float* conv_b = (const float*)d_in[5];
    const float* W_xprj = (const float*)d_in[6];
    const float* W_dt   = (const float*)d_in[7];
    const float* b_dt   = (const float*)d_in[8];
    const float* A_log  = (const float*)d_in[9];
    const float* Dp     = (const float*)d_in[10];
    const float* W_out  = (const float*)d_in[11];
    float* out = (float*)d_out;

    float *xdbl, *xdblp;
    __nv_bfloat16 *xz, *dt_bf, *h_bf, *xc_bf, *dtr_bf, *y_bf;
    __nv_bfloat16 *Win_bf, *Wxp_bf, *Wdt_bf, *Wout_bf;
    cudaGetSymbolAddress((void**)&xz,      g_xz);
    cudaGetSymbolAddress((void**)&xdbl,    g_xdbl);
    cudaGetSymbolAddress((void**)&xdblp,   g_xdbl_part);
    cudaGetSymbolAddress((void**)&dt_bf,   g_dt_bf);
    cudaGetSymbolAddress((void**)&h_bf,    g_h_bf);
    cudaGetSymbolAddress((void**)&xc_bf,   g_xc_bf);
    cudaGetSymbolAddress((void**)&dtr_bf,  g_dtr_bf);
    cudaGetSymbolAddress((void**)&y_bf,    g_y_bf);
    cudaGetSymbolAddress((void**)&Win_bf,  g_Win_bf);
    cudaGetSymbolAddress((void**)&Wxp_bf,  g_Wxp_bf);
    cudaGetSymbolAddress((void**)&Wdt_bf,  g_Wdt_bf);
    cudaGetSymbolAddress((void**)&Wout_bf, g_Wout_bf);

    cudaFuncSetAttribute(gemm_mma_kernel<0>,
        cudaFuncAttributeMaxDynamicSharedMemorySize, GEMM_SMEM_BYTES);
    cudaFuncSetAttribute(gemm_mma_kernel<1>,
        cudaFuncAttributeMaxDynamicSharedMemorySize, GEMM_SMEM_BYTES);
    cudaFuncSetAttribute(gemm_mma_kernel<2>,
        cudaFuncAttributeMaxDynamicSharedMemorySize, GEMM_SMEM_BYTES);
    cudaFuncSetAttribute(gemm_mma_kernel<3>,
        cudaFuncAttributeMaxDynamicSharedMemorySize, GEMM_SMEM_BYTES);

    // 0. weight conversions (single launch)
    cvt_all_kernel<<<(S0+S1+S2+S3 + 255)/256, 256>>>(
        (const float4*)W_in,  (__nv_bfloat162*)Win_bf,
        (const float4*)W_xprj,(__nv_bfloat162*)Wxp_bf,
        (const float4*)W_dt,  (__nv_bfloat162*)Wdt_bf,
        (const float4*)W_out, (__nv_bfloat162*)Wout_bf);

    // 1. LayerNorm -> bf16
    ln_kernel<<<TOK, 256>>>(x, ln_g, ln_b, h_bf);

    // 2. xz = h @ W_in^T  (2048 x 3072 x 768), bf16 out
    gemm_mma_kernel<0><<<dim3(2*DI/128, TOK/64, 1), 128, GEMM_SMEM_BYTES>>>(
        h_bf, DM, Win_bf, DM, xz, 2*DI, nullptr, 2*DI, DM, DM, 0);

    // 3. depthwise conv + silu -> xc (bf16)
    conv_silu_kernel<<<(TOK/2)*(DI/8)/256, 256>>>(xz, conv_w, conv_b, xc_bf);

    // 4. x_dbl = xc @ W_xproj^T  (2048 x 80 x 1536), split-K=8 -> reduce
    gemm_mma_kernel<3><<<dim3(1, TOK/64, KSPLIT), 128, GEMM_SMEM_BYTES>>>(
        xc_bf, DI, Wxp_bf, DI, xdblp, XPROJ_N, nullptr, XPROJ_N, DI, DI/KSPLIT,
        (size_t)PART_STRIDE);
    reduce_ksplit_kernel<<<(TOK*XPROJ_N)/256, 256>>>(xdblp, xdbl, dtr_bf);

    // 5. dt = softplus(dt_r @ W_dt^T + b_dt)  (2048 x 1536 x 48), bf16 out
    gemm_mma_kernel<1><<<dim3(DI/128, TOK/64, 1), 128, GEMM_SMEM_BYTES>>>(
        dtr_bf, DR, Wdt_bf, DR, dt_bf, DI, b_dt, DI, DR, DR, 0);

    // 6. selective scan -> y (gated, bf16)
    scan_kernel<<<dim3(DI/16, BB), 256>>>(dt_bf, xc_bf, xz, xdbl, A_log, Dp, y_bf);

    // 7. out = x + y @ W_out^T  (2048 x 768 x 1536)
    gemm_mma_kernel<2><<<dim3(DM/128, TOK/64, 1), 128, GEMM_SMEM_BYTES>>>(
        y_bf, DI, Wout_bf, DI, out, DM, x, DM, DI, DI, 0);
}